// round 16
// baseline (speedup 1.0000x reference)
#include <cuda_runtime.h>
#include <cuda_fp16.h>
#include <math.h>
#include <cstdint>

#define N_NODES 16384
#define N_EDGES 131072

typedef uint32_t u32;

// ---------------- scratch (static device arrays) ---------------------------
__device__ int    g_counts[N_NODES];
__device__ int    g_cursor[N_NODES];
__device__ int    g_offsets[N_NODES + 1];
__device__ int    g_done;
__device__ int    g_sendp[N_EDGES];         // CSR pos -> sender node
__device__ float4 g_efp[N_EDGES];           // CSR pos -> edge features
__device__ __align__(16) float g_radp[(size_t)N_EDGES * 8];  // CSR-ordered radial
__device__ __half g_w[(size_t)N_EDGES * 384];   // CSR-ordered MLP weights (fp16)

// fragment-linear B operands: per (tile, kt, lane): [hi0, hi1, lo0, lo1] u32
__device__ __align__(16) __half g_b2f[8  * 4 * 32 * 4 * 2];
__device__ __align__(16) __half g_b3f[48 * 4 * 32 * 4 * 2];

// ---------------- helpers ----------------------------------------------------
__device__ __forceinline__ void mma_f16(float* c, const u32* a, u32 b0, u32 b1) {
    asm volatile(
        "mma.sync.aligned.m16n8k16.row.col.f32.f16.f16.f32 "
        "{%0,%1,%2,%3}, {%4,%5,%6,%7}, {%8,%9}, {%0,%1,%2,%3};"
        : "+f"(c[0]), "+f"(c[1]), "+f"(c[2]), "+f"(c[3])
        : "r"(a[0]), "r"(a[1]), "r"(a[2]), "r"(a[3]), "r"(b0), "r"(b1));
}
__device__ __forceinline__ u32 pkh2(float a, float b) {
    __half2 v = __floats2half2_rn(a, b);
    return *(u32*)&v;
}
__device__ __forceinline__ float silu_f(float x) {
    return x / (1.0f + __expf(-x));
}

#define SCALE_H1 0.35355339059327373f   // 1/sqrt(8)
#define SCALE_H2 0.125f                 // 1/sqrt(64)
#define SCALE_W  0.04419417382415922f   // 0.125 * 1/sqrt(8)
#define INV_SQRT3 0.57735026918962576f

// ---------------- fused init: zero counts + frag-linear B prep --------------
__global__ void k_init(const float* __restrict__ w2, const float* __restrict__ w3) {
    if (blockIdx.x == 0 && threadIdx.x == 0) g_done = 0;
    if (blockIdx.x < 64) {
        int i = blockIdx.x * 256 + threadIdx.x;
        g_counts[i] = 0;
        return;
    }
    int idx = (int)(blockIdx.x - 64) * 256 + threadIdx.x;   // 448*64 total
    if (idx >= 448 * 64) return;
    int n = idx >> 6, k = idx & 63;
    float v;
    if (n < 64) v = w2[k * 64 + n];
    else        v = w3[k * 384 + (n - 64)];
    __half h = __float2half_rn(v);
    __half l = __float2half_rn(v - __half2float(h));

    int m = (n < 64) ? n : (n - 64);
    int w = k >> 1, hp = k & 1;         // u32 word index, half-within-word
    int ntile = m >> 3, qrr = m & 7;
    int kt = w >> 3, r = w & 7;
    int qcc = r & 3, pos = r >> 2;
    int ln = qrr * 4 + qcc;
    size_t slot = ((size_t)(ntile * 4 + kt) * 32 + ln) * 4;
    __half* arr = (n < 64) ? g_b2f : g_b3f;
    arr[(slot + pos) * 2 + hp]     = h;
    arr[(slot + 2 + pos) * 2 + hp] = l;
}

// ---------------- fused hist + scan (last-CTA does the scan) ----------------
__global__ void k_histscan(const int* __restrict__ recv) {
    int e = blockIdx.x * 256 + threadIdx.x;
    atomicAdd(&g_counts[recv[e]], 1);
    __threadfence();
    __shared__ int is_last;
    __syncthreads();
    if (threadIdx.x == 0)
        is_last = (atomicAdd(&g_done, 1) == (N_EDGES / 256) - 1);
    __syncthreads();
    if (!is_last) return;

    int t = threadIdx.x;
    int base = t * 64;
    int sum = 0;
#pragma unroll 8
    for (int i = 0; i < 64; i++) sum += g_counts[base + i];
    __shared__ int part[256];
    part[t] = sum;
    __syncthreads();
    for (int off = 1; off < 256; off <<= 1) {
        int add = (t >= off) ? part[t - off] : 0;
        __syncthreads();
        part[t] += add;
        __syncthreads();
    }
    int run = part[t] - sum;
#pragma unroll 8
    for (int i = 0; i < 64; i++) {
        int c = g_counts[base + i];
        g_offsets[base + i] = run;
        g_cursor[base + i] = 0;
        run += c;
    }
    if (t == 255) g_offsets[N_NODES] = run;
}

__global__ void k_scatter(const int* __restrict__ recv,
                          const int* __restrict__ send,
                          const float* __restrict__ ef,
                          const float* __restrict__ rad) {
    int e = blockIdx.x * blockDim.x + threadIdx.x;
    if (e < N_EDGES) {
        int r = recv[e];
        int pos = g_offsets[r] + atomicAdd(&g_cursor[r], 1);
        g_sendp[pos] = send[e];
        g_efp[pos] = *(const float4*)(ef + (size_t)e * 4);
        float4 r0 = *(const float4*)(rad + (size_t)e * 8);
        float4 r1 = *(const float4*)(rad + (size_t)e * 8 + 4);
        *(float4*)(g_radp + (size_t)pos * 8)     = r0;
        *(float4*)(g_radp + (size_t)pos * 8 + 4) = r1;
    }
}

// ---------------- MMA MLP: 1024 threads (32 warps), 256 edges/CTA -----------
// warp pair per 16-row tile: even warp = N-half 0, odd = N-half 1.
// B fragments read via LDG.128 from frag-linear globals (L1-resident).
#define STRD 36
#define O_AHI 0               // 256 rows x 36 (layer-1 output)
#define O_A2  9216            // 16 tiles x 512 (A-frag exchange, lane-major)
#define O_W1  17408           // 512 floats
#define SMEM_U32 17920
#define SMEM_MLP (SMEM_U32 * 4)   // 71680 B

__global__ void __launch_bounds__(1024) k_mlp_mma(const float* __restrict__ w1)
{
    extern __shared__ u32 smu[];
    int t = threadIdx.x, wid = t >> 5, lane = t & 31;
    int qr = lane >> 2, qc = lane & 3;
    int rt = wid >> 1, ch = wid & 1;     // row-tile 0..15, col-half 0..1
    int ebase = blockIdx.x * 256;

    // ---- stage w1 only ----
    if (t < 512) {
        float* sw1 = (float*)(smu + O_W1);
        sw1[t] = w1[t];
    }
    __syncthreads();

    // ---- layer 1 (scalar): H1 = silu(Rcsr @ W1 / sqrt8) -> fp16 ----
    if (t < 512) {
        const float* sw1 = (const float*)(smu + O_W1);
        int row = t & 255, gh = t >> 8;           // gh: 0 -> g 0..3, 1 -> g 4..7
        const float4* rp = (const float4*)(g_radp + (size_t)(ebase + row) * 8);
        float4 ra = rp[0], rb = rp[1];
        float rr[8] = {ra.x, ra.y, ra.z, ra.w, rb.x, rb.y, rb.z, rb.w};
#pragma unroll
        for (int gi = 0; gi < 4; gi++) {
            int g = gh * 4 + gi;
            float acc[8] = {0, 0, 0, 0, 0, 0, 0, 0};
#pragma unroll
            for (int k = 0; k < 8; k++) {
                float rv = rr[k];
                const float* wrow = sw1 + k * 64 + g * 8;
#pragma unroll
                for (int jj = 0; jj < 8; jj++) acc[jj] = fmaf(rv, wrow[jj], acc[jj]);
            }
            u32 ph[4];
#pragma unroll
            for (int p = 0; p < 4; p++) {
                float x0 = silu_f(acc[2 * p]     * SCALE_H1);
                float x1 = silu_f(acc[2 * p + 1] * SCALE_H1);
                ph[p] = pkh2(x0, x1);
            }
            *(uint4*)&smu[O_AHI + row * STRD + g * 4] = make_uint4(ph[0], ph[1], ph[2], ph[3]);
        }
    }
    __syncthreads();

    // ---- layer 2 MMA: C2[256x64]; warp = (row-tile rt, col-half ch) ----
    int r0 = rt * 16 + qr;
    u32 af[4][4];
#pragma unroll
    for (int kt = 0; kt < 4; kt++) {
        int o = kt * 8 + qc;
        af[kt][0] = smu[O_AHI + r0 * STRD + o];
        af[kt][1] = smu[O_AHI + (r0 + 8) * STRD + o];
        af[kt][2] = smu[O_AHI + r0 * STRD + o + 4];
        af[kt][3] = smu[O_AHI + (r0 + 8) * STRD + o + 4];
    }

    float acc2[4][4];
#pragma unroll
    for (int nt = 0; nt < 4; nt++)
#pragma unroll
        for (int j = 0; j < 4; j++) acc2[nt][j] = 0.f;

    const uint4* b2 = (const uint4*)g_b2f;
#pragma unroll
    for (int nt = 0; nt < 4; nt++) {
        int tile = ch * 4 + nt;
#pragma unroll
        for (int kt = 0; kt < 4; kt++) {
            uint4 b = __ldg(&b2[(tile * 4 + kt) * 32 + lane]);
            mma_f16(acc2[nt], af[kt], b.x, b.y);
            mma_f16(acc2[nt], af[kt], b.z, b.w);
        }
    }

    // ---- C2 -> layer-3 A fragments; publish this warp's 2 k-tiles ----------
#pragma unroll
    for (int kt2 = 0; kt2 < 2; kt2++) {
        int ktg = ch * 2 + kt2;
        u32 f0 = pkh2(silu_f(acc2[2 * kt2][0] * SCALE_H2),
                      silu_f(acc2[2 * kt2][1] * SCALE_H2));
        u32 f1 = pkh2(silu_f(acc2[2 * kt2][2] * SCALE_H2),
                      silu_f(acc2[2 * kt2][3] * SCALE_H2));
        u32 f2 = pkh2(silu_f(acc2[2 * kt2 + 1][0] * SCALE_H2),
                      silu_f(acc2[2 * kt2 + 1][1] * SCALE_H2));
        u32 f3 = pkh2(silu_f(acc2[2 * kt2 + 1][2] * SCALE_H2),
                      silu_f(acc2[2 * kt2 + 1][3] * SCALE_H2));
        int base = O_A2 + rt * 512 + ktg * 128;
        smu[base + lane]       = f0;
        smu[base + 32 + lane]  = f1;
        smu[base + 64 + lane]  = f2;
        smu[base + 96 + lane]  = f3;
    }
    __syncthreads();

    // load all 4 k-tiles of this row-tile's A-fragments
#pragma unroll
    for (int kt = 0; kt < 4; kt++) {
        int base = O_A2 + rt * 512 + kt * 128;
        af[kt][0] = smu[base + lane];
        af[kt][1] = smu[base + 32 + lane];
        af[kt][2] = smu[base + 64 + lane];
        af[kt][3] = smu[base + 96 + lane];
    }

    // ---- layer 3: warp computes its 16 rows x 192 cols (half ch) -----------
    size_t er0 = (size_t)(ebase + r0) * 384;
    size_t er1 = (size_t)(ebase + r0 + 8) * 384;
    const uint4* b3 = (const uint4*)g_b3f;

#pragma unroll 2
    for (int nt = 0; nt < 24; nt++) {
        int tile = ch * 24 + nt;
        float acc[4] = {0.f, 0.f, 0.f, 0.f};
#pragma unroll
        for (int kt = 0; kt < 4; kt++) {
            uint4 b = __ldg(&b3[(tile * 4 + kt) * 32 + lane]);
            mma_f16(acc, af[kt], b.x, b.y);
            mma_f16(acc, af[kt], b.z, b.w);
        }
        int col = ch * 192 + nt * 8 + qc * 2;
        *(__half2*)&g_w[er0 + col] = __floats2half2_rn(acc[0] * SCALE_W, acc[1] * SCALE_W);
        *(__half2*)&g_w[er1 + col] = __floats2half2_rn(acc[2] * SCALE_W, acc[3] * SCALE_W);
    }
}

// ---------------- gather / tensor-product / accumulate ---------------------
// warp per receiver node, REVERSE order (L2 reuse of g_w tail) — R7 winner
__global__ void __launch_bounds__(256) k_gather(
    const float* __restrict__ nf,
    float*       __restrict__ out)
{
    int gwi = (blockIdx.x * blockDim.x + threadIdx.x) >> 5;
    int lane = threadIdx.x & 31;
    if (gwi >= N_NODES) return;
    int gw = N_NODES - 1 - gwi;

    int beg = g_offsets[gw], end = g_offsets[gw + 1];
    int m0 = lane * 2;

    float s0a = 0.f, s0b = 0.f, s1a = 0.f, s1b = 0.f, s2a = 0.f, s2b = 0.f;
    float v0a0=0.f,v0a1=0.f,v0a2=0.f, v0b0=0.f,v0b1=0.f,v0b2=0.f;
    float v1a0=0.f,v1a1=0.f,v1a2=0.f, v1b0=0.f,v1b1=0.f,v1b2=0.f;
    float v2a0=0.f,v2a1=0.f,v2a2=0.f, v2b0=0.f,v2b1=0.f,v2b2=0.f;

    for (int p = beg; p < end; p++) {
        int s = g_sendp[p];
        float4 efv = g_efp[p];
        float es = efv.x, e0 = efv.y, e1 = efv.z, e2 = efv.w;

        const float* row = nf + (size_t)s * 256;
        float2 se = *(const float2*)(row + m0);
        float2 va = *(const float2*)(row + 64 + 3 * m0);
        float2 vb = *(const float2*)(row + 66 + 3 * m0);
        float2 vc = *(const float2*)(row + 68 + 3 * m0);

        const __half* wr = g_w + (size_t)p * 384;
        float2 w0 = __half22float2(*(const __half2*)(wr + m0));
        float2 w1 = __half22float2(*(const __half2*)(wr + 64 + m0));
        float2 w2 = __half22float2(*(const __half2*)(wr + 128 + m0));
        float2 w3 = __half22float2(*(const __half2*)(wr + 192 + m0));
        float2 w4 = __half22float2(*(const __half2*)(wr + 256 + m0));
        float2 w5 = __half22float2(*(const __half2*)(wr + 320 + m0));

        {
            float S = se.x, V0 = va.x, V1 = va.y, V2 = vb.x;
            float Ses = S * es;
            s0a = fmaf(S, w0.x, s0a);
            s1a = fmaf(Ses, w1.x, s1a);
            float dot = fmaf(V0, e0, fmaf(V1, e1, V2 * e2));
            s2a = fmaf(dot * INV_SQRT3, w2.x, s2a);
            v0a0 = fmaf(V0, w3.x, v0a0); v0a1 = fmaf(V1, w3.x, v0a1); v0a2 = fmaf(V2, w3.x, v0a2);
            v1a0 = fmaf(S * e0, w4.x, v1a0); v1a1 = fmaf(S * e1, w4.x, v1a1); v1a2 = fmaf(S * e2, w4.x, v1a2);
            v2a0 = fmaf(V0 * es, w5.x, v2a0); v2a1 = fmaf(V1 * es, w5.x, v2a1); v2a2 = fmaf(V2 * es, w5.x, v2a2);
        }
        {
            float S = se.y, V0 = vb.y, V1 = vc.x, V2 = vc.y;
            float Ses = S * es;
            s0b = fmaf(S, w0.y, s0b);
            s1b = fmaf(Ses, w1.y, s1b);
            float dot = fmaf(V0, e0, fmaf(V1, e1, V2 * e2));
            s2b = fmaf(dot * INV_SQRT3, w2.y, s2b);
            v0b0 = fmaf(V0, w3.y, v0b0); v0b1 = fmaf(V1, w3.y, v0b1); v0b2 = fmaf(V2, w3.y, v0b2);
            v1b0 = fmaf(S * e0, w4.y, v1b0); v1b1 = fmaf(S * e1, w4.y, v1b1); v1b2 = fmaf(S * e2, w4.y, v1b2);
            v2b0 = fmaf(V0 * es, w5.y, v2b0); v2b1 = fmaf(V1 * es, w5.y, v2b1); v2b2 = fmaf(V2 * es, w5.y, v2b2);
        }
    }

    float* o = out + (size_t)gw * 768;
    *(float2*)(o + m0)       = make_float2(s0a, s0b);
    *(float2*)(o + 64 + m0)  = make_float2(s1a, s1b);
    *(float2*)(o + 128 + m0) = make_float2(s2a, s2b);
    {
        int base = 192 + m0 * 3;
        *(float2*)(o + base)     = make_float2(v0a0, v0a1);
        *(float2*)(o + base + 2) = make_float2(v0a2, v0b0);
        *(float2*)(o + base + 4) = make_float2(v0b1, v0b2);
    }
    {
        int base = 192 + (64 + m0) * 3;
        *(float2*)(o + base)     = make_float2(v1a0, v1a1);
        *(float2*)(o + base + 2) = make_float2(v1a2, v1b0);
        *(float2*)(o + base + 4) = make_float2(v1b1, v1b2);
    }
    {
        int base = 192 + (128 + m0) * 3;
        *(float2*)(o + base)     = make_float2(v2a0, v2a1);
        *(float2*)(o + base + 2) = make_float2(v2a2, v2b0);
        *(float2*)(o + base + 4) = make_float2(v2b1, v2b2);
    }
}

// ---------------- launch ----------------------------------------------------
extern "C" void kernel_launch(void* const* d_in, const int* in_sizes, int n_in,
                              void* d_out, int out_size) {
    const float* nf   = (const float*)d_in[0];
    const float* ef   = (const float*)d_in[1];
    const float* rad  = (const float*)d_in[2];
    const float* w1   = (const float*)d_in[3];
    const float* w2   = (const float*)d_in[4];
    const float* w3   = (const float*)d_in[5];
    const int*   send = (const int*)d_in[6];
    const int*   recv = (const int*)d_in[7];
    float* out = (float*)d_out;

    cudaFuncSetAttribute(k_mlp_mma, cudaFuncAttributeMaxDynamicSharedMemorySize, SMEM_MLP);

    k_init     <<<64 + 112, 256>>>(w2, w3);
    k_histscan <<<N_EDGES / 256, 256>>>(recv);
    k_scatter  <<<N_EDGES / 256, 256>>>(recv, send, ef, rad);
    k_mlp_mma  <<<N_EDGES / 256, 1024, SMEM_MLP>>>(w1);
    k_gather   <<<(N_NODES * 32) / 256, 256>>>(nf, out);
}

// round 17
// speedup vs baseline: 1.0813x; 1.0813x over previous
#include <cuda_runtime.h>
#include <cuda_fp16.h>
#include <math.h>
#include <cstdint>

#define N_NODES 16384
#define N_EDGES 131072

typedef uint32_t u32;

// ---------------- scratch (static device arrays) ---------------------------
__device__ int    g_counts[N_NODES];
__device__ int    g_cursor[N_NODES];
__device__ int    g_offsets[N_NODES + 1];
__device__ int    g_done;
__device__ int    g_sendp[N_EDGES];         // CSR pos -> sender node
__device__ float4 g_efp[N_EDGES];           // CSR pos -> edge features
__device__ __align__(16) float g_radp[(size_t)N_EDGES * 8];  // CSR-ordered radial
__device__ __half g_w[(size_t)N_EDGES * 384];   // CSR-ordered MLP weights (fp16)

// fragment-linear B operands: per (tile, kt, lane): [hi0, hi1, lo0, lo1] u32
__device__ __align__(16) __half g_b2f[8  * 4 * 32 * 4 * 2];
__device__ __align__(16) __half g_b3f[48 * 4 * 32 * 4 * 2];

// ---------------- helpers ----------------------------------------------------
__device__ __forceinline__ void mma_f16(float* c, const u32* a, u32 b0, u32 b1) {
    asm volatile(
        "mma.sync.aligned.m16n8k16.row.col.f32.f16.f16.f32 "
        "{%0,%1,%2,%3}, {%4,%5,%6,%7}, {%8,%9}, {%0,%1,%2,%3};"
        : "+f"(c[0]), "+f"(c[1]), "+f"(c[2]), "+f"(c[3])
        : "r"(a[0]), "r"(a[1]), "r"(a[2]), "r"(a[3]), "r"(b0), "r"(b1));
}
__device__ __forceinline__ u32 pkh2(float a, float b) {
    __half2 v = __floats2half2_rn(a, b);
    return *(u32*)&v;
}
__device__ __forceinline__ float silu_f(float x) {
    return x / (1.0f + __expf(-x));
}

#define SCALE_H1 0.35355339059327373f   // 1/sqrt(8)
#define SCALE_H2 0.125f                 // 1/sqrt(64)
#define SCALE_W  0.04419417382415922f   // 0.125 * 1/sqrt(8)
#define INV_SQRT3 0.57735026918962576f

// ---------------- fused init: zero counts + frag-linear B prep --------------
__global__ void k_init(const float* __restrict__ w2, const float* __restrict__ w3) {
    if (blockIdx.x == 0 && threadIdx.x == 0) g_done = 0;
    if (blockIdx.x < 64) {
        int i = blockIdx.x * 256 + threadIdx.x;
        g_counts[i] = 0;
        return;
    }
    int idx = (int)(blockIdx.x - 64) * 256 + threadIdx.x;   // 448*64 total
    if (idx >= 448 * 64) return;
    int n = idx >> 6, k = idx & 63;
    float v;
    if (n < 64) v = w2[k * 64 + n];
    else        v = w3[k * 384 + (n - 64)];
    __half h = __float2half_rn(v);
    __half l = __float2half_rn(v - __half2float(h));

    int m = (n < 64) ? n : (n - 64);
    int w = k >> 1, hp = k & 1;         // u32 word index, half-within-word
    int ntile = m >> 3, qrr = m & 7;
    int kt = w >> 3, r = w & 7;
    int qcc = r & 3, pos = r >> 2;
    int ln = qrr * 4 + qcc;
    size_t slot = ((size_t)(ntile * 4 + kt) * 32 + ln) * 4;
    __half* arr = (n < 64) ? g_b2f : g_b3f;
    arr[(slot + pos) * 2 + hp]     = h;
    arr[(slot + 2 + pos) * 2 + hp] = l;
}

// ---------------- fused hist + scan (last-CTA does the scan) ----------------
__global__ void k_histscan(const int* __restrict__ recv) {
    int e = blockIdx.x * 256 + threadIdx.x;
    atomicAdd(&g_counts[recv[e]], 1);
    __threadfence();
    __shared__ int is_last;
    __syncthreads();
    if (threadIdx.x == 0)
        is_last = (atomicAdd(&g_done, 1) == (N_EDGES / 256) - 1);
    __syncthreads();
    if (!is_last) return;

    int t = threadIdx.x;
    int base = t * 64;
    int sum = 0;
#pragma unroll 8
    for (int i = 0; i < 64; i++) sum += g_counts[base + i];
    __shared__ int part[256];
    part[t] = sum;
    __syncthreads();
    for (int off = 1; off < 256; off <<= 1) {
        int add = (t >= off) ? part[t - off] : 0;
        __syncthreads();
        part[t] += add;
        __syncthreads();
    }
    int run = part[t] - sum;
#pragma unroll 8
    for (int i = 0; i < 64; i++) {
        int c = g_counts[base + i];
        g_offsets[base + i] = run;
        g_cursor[base + i] = 0;
        run += c;
    }
    if (t == 255) g_offsets[N_NODES] = run;
}

__global__ void k_scatter(const int* __restrict__ recv,
                          const int* __restrict__ send,
                          const float* __restrict__ ef,
                          const float* __restrict__ rad) {
    int e = blockIdx.x * blockDim.x + threadIdx.x;
    if (e < N_EDGES) {
        int r = recv[e];
        int pos = g_offsets[r] + atomicAdd(&g_cursor[r], 1);
        g_sendp[pos] = send[e];
        g_efp[pos] = *(const float4*)(ef + (size_t)e * 4);
        float4 r0 = *(const float4*)(rad + (size_t)e * 8);
        float4 r1 = *(const float4*)(rad + (size_t)e * 8 + 4);
        *(float4*)(g_radp + (size_t)pos * 8)     = r0;
        *(float4*)(g_radp + (size_t)pos * 8 + 4) = r1;
    }
}

// ---------------- MMA MLP: 1024 threads (32 warps), 256 edges/CTA -----------
// warp pair per 16-row tile: even warp = N-half 0, odd = N-half 1.
// B operands staged in smem (frag-linear) -> one LDS.128 per fragment-pair.
#define STRD 36
#define O_B2F 0               //  4096 u32
#define O_B3F 4096            // 24576 u32
#define O_AHI 28672           // 256 rows x 36 (layer-1 output)
#define O_A2  37888           // 16 tiles x 512 (A-frag exchange, lane-major)
#define O_W1  46080           // 512 floats
#define SMEM_U32 46592
#define SMEM_MLP (SMEM_U32 * 4)   // 186368 B

__global__ void __launch_bounds__(1024) k_mlp_mma(const float* __restrict__ w1)
{
    extern __shared__ u32 smu[];
    int t = threadIdx.x, wid = t >> 5, lane = t & 31;
    int qr = lane >> 2, qc = lane & 3;
    int rt = wid >> 1, ch = wid & 1;     // row-tile 0..15, col-half 0..1
    int ebase = blockIdx.x * 256;

    // ---- stage B operands (frag-linear) + w1 ----
    {
        const uint4* s2 = (const uint4*)g_b2f;
        uint4* d2 = (uint4*)(smu + O_B2F);
        if (t < 1024) d2[t] = s2[t];
        const uint4* s3 = (const uint4*)g_b3f;
        uint4* d3 = (uint4*)(smu + O_B3F);
        for (int i = t; i < 6144; i += 1024) d3[i] = s3[i];
        if (t < 512) {
            float* sw1 = (float*)(smu + O_W1);
            sw1[t] = w1[t];
        }
    }
    __syncthreads();

    // ---- layer 1 (scalar): H1 = silu(Rcsr @ W1 / sqrt8) -> fp16 ----
    if (t < 512) {
        const float* sw1 = (const float*)(smu + O_W1);
        int row = t & 255, gh = t >> 8;           // gh: 0 -> g 0..3, 1 -> g 4..7
        const float4* rp = (const float4*)(g_radp + (size_t)(ebase + row) * 8);
        float4 ra = rp[0], rb = rp[1];
        float rr[8] = {ra.x, ra.y, ra.z, ra.w, rb.x, rb.y, rb.z, rb.w};
#pragma unroll
        for (int gi = 0; gi < 4; gi++) {
            int g = gh * 4 + gi;
            float acc[8] = {0, 0, 0, 0, 0, 0, 0, 0};
#pragma unroll
            for (int k = 0; k < 8; k++) {
                float rv = rr[k];
                const float* wrow = sw1 + k * 64 + g * 8;
#pragma unroll
                for (int jj = 0; jj < 8; jj++) acc[jj] = fmaf(rv, wrow[jj], acc[jj]);
            }
            u32 ph[4];
#pragma unroll
            for (int p = 0; p < 4; p++) {
                float x0 = silu_f(acc[2 * p]     * SCALE_H1);
                float x1 = silu_f(acc[2 * p + 1] * SCALE_H1);
                ph[p] = pkh2(x0, x1);
            }
            *(uint4*)&smu[O_AHI + row * STRD + g * 4] = make_uint4(ph[0], ph[1], ph[2], ph[3]);
        }
    }
    __syncthreads();

    // ---- layer 2 MMA: C2[256x64]; warp = (row-tile rt, col-half ch) ----
    int r0 = rt * 16 + qr;
    u32 af[4][4];
#pragma unroll
    for (int kt = 0; kt < 4; kt++) {
        int o = kt * 8 + qc;
        af[kt][0] = smu[O_AHI + r0 * STRD + o];
        af[kt][1] = smu[O_AHI + (r0 + 8) * STRD + o];
        af[kt][2] = smu[O_AHI + r0 * STRD + o + 4];
        af[kt][3] = smu[O_AHI + (r0 + 8) * STRD + o + 4];
    }

    float acc2[4][4];
#pragma unroll
    for (int nt = 0; nt < 4; nt++)
#pragma unroll
        for (int j = 0; j < 4; j++) acc2[nt][j] = 0.f;

#pragma unroll
    for (int nt = 0; nt < 4; nt++) {
        int tile = ch * 4 + nt;
#pragma unroll
        for (int kt = 0; kt < 4; kt++) {
            uint4 b = *(const uint4*)&smu[O_B2F + (tile * 4 + kt) * 128 + lane * 4];
            mma_f16(acc2[nt], af[kt], b.x, b.y);
            mma_f16(acc2[nt], af[kt], b.z, b.w);
        }
    }

    // ---- C2 -> layer-3 A fragments; publish this warp's 2 k-tiles ----------
#pragma unroll
    for (int kt2 = 0; kt2 < 2; kt2++) {
        int ktg = ch * 2 + kt2;
        u32 f0 = pkh2(silu_f(acc2[2 * kt2][0] * SCALE_H2),
                      silu_f(acc2[2 * kt2][1] * SCALE_H2));
        u32 f1 = pkh2(silu_f(acc2[2 * kt2][2] * SCALE_H2),
                      silu_f(acc2[2 * kt2][3] * SCALE_H2));
        u32 f2 = pkh2(silu_f(acc2[2 * kt2 + 1][0] * SCALE_H2),
                      silu_f(acc2[2 * kt2 + 1][1] * SCALE_H2));
        u32 f3 = pkh2(silu_f(acc2[2 * kt2 + 1][2] * SCALE_H2),
                      silu_f(acc2[2 * kt2 + 1][3] * SCALE_H2));
        int base = O_A2 + rt * 512 + ktg * 128;
        smu[base + lane]       = f0;
        smu[base + 32 + lane]  = f1;
        smu[base + 64 + lane]  = f2;
        smu[base + 96 + lane]  = f3;
    }
    __syncthreads();

    // load all 4 k-tiles of this row-tile's A-fragments
#pragma unroll
    for (int kt = 0; kt < 4; kt++) {
        int base = O_A2 + rt * 512 + kt * 128;
        af[kt][0] = smu[base + lane];
        af[kt][1] = smu[base + 32 + lane];
        af[kt][2] = smu[base + 64 + lane];
        af[kt][3] = smu[base + 96 + lane];
    }

    // ---- layer 3: warp computes its 16 rows x 192 cols (half ch) -----------
    size_t er0 = (size_t)(ebase + r0) * 384;
    size_t er1 = (size_t)(ebase + r0 + 8) * 384;

#pragma unroll 2
    for (int nt = 0; nt < 24; nt++) {
        int tile = ch * 24 + nt;
        float acc[4] = {0.f, 0.f, 0.f, 0.f};
#pragma unroll
        for (int kt = 0; kt < 4; kt++) {
            uint4 b = *(const uint4*)&smu[O_B3F + (tile * 4 + kt) * 128 + lane * 4];
            mma_f16(acc, af[kt], b.x, b.y);
            mma_f16(acc, af[kt], b.z, b.w);
        }
        int col = ch * 192 + nt * 8 + qc * 2;
        *(__half2*)&g_w[er0 + col] = __floats2half2_rn(acc[0] * SCALE_W, acc[1] * SCALE_W);
        *(__half2*)&g_w[er1 + col] = __floats2half2_rn(acc[2] * SCALE_W, acc[3] * SCALE_W);
    }
}

// ---------------- gather / tensor-product / accumulate ---------------------
// warp per receiver node, REVERSE order (L2 reuse of g_w tail) — R7 winner
__global__ void __launch_bounds__(256) k_gather(
    const float* __restrict__ nf,
    float*       __restrict__ out)
{
    int gwi = (blockIdx.x * blockDim.x + threadIdx.x) >> 5;
    int lane = threadIdx.x & 31;
    if (gwi >= N_NODES) return;
    int gw = N_NODES - 1 - gwi;

    int beg = g_offsets[gw], end = g_offsets[gw + 1];
    int m0 = lane * 2;

    float s0a = 0.f, s0b = 0.f, s1a = 0.f, s1b = 0.f, s2a = 0.f, s2b = 0.f;
    float v0a0=0.f,v0a1=0.f,v0a2=0.f, v0b0=0.f,v0b1=0.f,v0b2=0.f;
    float v1a0=0.f,v1a1=0.f,v1a2=0.f, v1b0=0.f,v1b1=0.f,v1b2=0.f;
    float v2a0=0.f,v2a1=0.f,v2a2=0.f, v2b0=0.f,v2b1=0.f,v2b2=0.f;

    for (int p = beg; p < end; p++) {
        int s = g_sendp[p];
        float4 efv = g_efp[p];
        float es = efv.x, e0 = efv.y, e1 = efv.z, e2 = efv.w;

        const float* row = nf + (size_t)s * 256;
        float2 se = *(const float2*)(row + m0);
        float2 va = *(const float2*)(row + 64 + 3 * m0);
        float2 vb = *(const float2*)(row + 66 + 3 * m0);
        float2 vc = *(const float2*)(row + 68 + 3 * m0);

        const __half* wr = g_w + (size_t)p * 384;
        float2 w0 = __half22float2(*(const __half2*)(wr + m0));
        float2 w1 = __half22float2(*(const __half2*)(wr + 64 + m0));
        float2 w2 = __half22float2(*(const __half2*)(wr + 128 + m0));
        float2 w3 = __half22float2(*(const __half2*)(wr + 192 + m0));
        float2 w4 = __half22float2(*(const __half2*)(wr + 256 + m0));
        float2 w5 = __half22float2(*(const __half2*)(wr + 320 + m0));

        {
            float S = se.x, V0 = va.x, V1 = va.y, V2 = vb.x;
            float Ses = S * es;
            s0a = fmaf(S, w0.x, s0a);
            s1a = fmaf(Ses, w1.x, s1a);
            float dot = fmaf(V0, e0, fmaf(V1, e1, V2 * e2));
            s2a = fmaf(dot * INV_SQRT3, w2.x, s2a);
            v0a0 = fmaf(V0, w3.x, v0a0); v0a1 = fmaf(V1, w3.x, v0a1); v0a2 = fmaf(V2, w3.x, v0a2);
            v1a0 = fmaf(S * e0, w4.x, v1a0); v1a1 = fmaf(S * e1, w4.x, v1a1); v1a2 = fmaf(S * e2, w4.x, v1a2);
            v2a0 = fmaf(V0 * es, w5.x, v2a0); v2a1 = fmaf(V1 * es, w5.x, v2a1); v2a2 = fmaf(V2 * es, w5.x, v2a2);
        }
        {
            float S = se.y, V0 = vb.y, V1 = vc.x, V2 = vc.y;
            float Ses = S * es;
            s0b = fmaf(S, w0.y, s0b);
            s1b = fmaf(Ses, w1.y, s1b);
            float dot = fmaf(V0, e0, fmaf(V1, e1, V2 * e2));
            s2b = fmaf(dot * INV_SQRT3, w2.y, s2b);
            v0b0 = fmaf(V0, w3.y, v0b0); v0b1 = fmaf(V1, w3.y, v0b1); v0b2 = fmaf(V2, w3.y, v0b2);
            v1b0 = fmaf(S * e0, w4.y, v1b0); v1b1 = fmaf(S * e1, w4.y, v1b1); v1b2 = fmaf(S * e2, w4.y, v1b2);
            v2b0 = fmaf(V0 * es, w5.y, v2b0); v2b1 = fmaf(V1 * es, w5.y, v2b1); v2b2 = fmaf(V2 * es, w5.y, v2b2);
        }
    }

    float* o = out + (size_t)gw * 768;
    *(float2*)(o + m0)       = make_float2(s0a, s0b);
    *(float2*)(o + 64 + m0)  = make_float2(s1a, s1b);
    *(float2*)(o + 128 + m0) = make_float2(s2a, s2b);
    {
        int base = 192 + m0 * 3;
        *(float2*)(o + base)     = make_float2(v0a0, v0a1);
        *(float2*)(o + base + 2) = make_float2(v0a2, v0b0);
        *(float2*)(o + base + 4) = make_float2(v0b1, v0b2);
    }
    {
        int base = 192 + (64 + m0) * 3;
        *(float2*)(o + base)     = make_float2(v1a0, v1a1);
        *(float2*)(o + base + 2) = make_float2(v1a2, v1b0);
        *(float2*)(o + base + 4) = make_float2(v1b1, v1b2);
    }
    {
        int base = 192 + (128 + m0) * 3;
        *(float2*)(o + base)     = make_float2(v2a0, v2a1);
        *(float2*)(o + base + 2) = make_float2(v2a2, v2b0);
        *(float2*)(o + base + 4) = make_float2(v2b1, v2b2);
    }
}

// ---------------- launch ----------------------------------------------------
extern "C" void kernel_launch(void* const* d_in, const int* in_sizes, int n_in,
                              void* d_out, int out_size) {
    const float* nf   = (const float*)d_in[0];
    const float* ef   = (const float*)d_in[1];
    const float* rad  = (const float*)d_in[2];
    const float* w1   = (const float*)d_in[3];
    const float* w2   = (const float*)d_in[4];
    const float* w3   = (const float*)d_in[5];
    const int*   send = (const int*)d_in[6];
    const int*   recv = (const int*)d_in[7];
    float* out = (float*)d_out;

    cudaFuncSetAttribute(k_mlp_mma, cudaFuncAttributeMaxDynamicSharedMemorySize, SMEM_MLP);

    k_init     <<<64 + 112, 256>>>(w2, w3);
    k_histscan <<<N_EDGES / 256, 256>>>(recv);
    k_scatter  <<<N_EDGES / 256, 256>>>(recv, send, ef, rad);
    k_mlp_mma  <<<N_EDGES / 256, 1024, SMEM_MLP>>>(w1);
    k_gather   <<<(N_NODES * 32) / 256, 256>>>(nf, out);
}